// round 10
// baseline (speedup 1.0000x reference)
#include <cuda_runtime.h>
#include <cstdint>

#define HW   512
#define NTHR 256
#define TPW  34
#define TPH  6
#define XS_CH (TPH * TPW)        // 204
#define TILES_PER_CTA 2
#define N_TILES 8192             // 4 batches * 16 * 128 tiles of 32x4

// smem layout (float offsets)
// Region at YS_OFF is time-shared: w0 staging (persistent) -> per tile: ys, then H.
// w0s (padded stride 52) lives at the TOP of the region so ys (6528) never overlaps it?
// -> No: ys needs the region during GEMM1 while w0s is still read. Keep w0s separate.
#define XS_OFF 0                 // [16][204] = 3264
#define YS_STR 136
#define YS_OFF 3264              // ys: [48][136] = 6528
#define H_STR  136
#define H_OFF  3264              // H: [128][136] -> 17408 (aliased with ys)
#define REGION 17408
#define W0_STR 52
#define W0_OFF (YS_OFF + REGION)        // 20672 ; [128][52] = 6656
#define W1_STR 132
#define W1_OFF (W0_OFF + 6656)          // 27328 ; [16][132] = 2112
#define B0_OFF (W1_OFF + 2112)          // 29440
#define MS_OFF (B0_OFF + 128)           // 29568
#define SM_FLOATS (MS_OFF + 128)        // 29696 floats = 118784 B

__device__ __forceinline__ float tf32f(float f) {
    uint32_t u;
    asm("cvt.rna.tf32.f32 %0, %1;" : "=r"(u) : "f"(f));
    return __uint_as_float(u);
}

// D += A(16x8) * B(8x8), tf32 inputs, f32 accumulate
__device__ __forceinline__ void mma8(float* d, const float* a, float b0, float b1) {
    asm("mma.sync.aligned.m16n8k8.row.col.f32.tf32.tf32.f32 "
        "{%0,%1,%2,%3}, {%4,%5,%6,%7}, {%8,%9}, {%0,%1,%2,%3};"
        : "+f"(d[0]), "+f"(d[1]), "+f"(d[2]), "+f"(d[3])
        : "r"(__float_as_uint(a[0])), "r"(__float_as_uint(a[1])),
          "r"(__float_as_uint(a[2])), "r"(__float_as_uint(a[3])),
          "r"(__float_as_uint(b0)), "r"(__float_as_uint(b1)));
}

__global__ __launch_bounds__(NTHR, 2)
void ca_mma_kernel(const float* __restrict__ x,
                   const float* __restrict__ w0,
                   const float* __restrict__ b0,
                   const float* __restrict__ w1,
                   const float* __restrict__ rand_u,
                   float* __restrict__ out)
{
    extern __shared__ float sm[];
    float* xs  = sm + XS_OFF;
    float* ys  = sm + YS_OFF;
    float* Hs  = sm + H_OFF;
    float* w0s = sm + W0_OFF;
    float* w1s = sm + W1_OFF;
    float* b0s = sm + B0_OFF;
    float* ms  = sm + MS_OFF;

    const int tid  = threadIdx.x;
    const int lane = tid & 31;
    const int wid  = tid >> 5;
    const int g    = lane >> 2;   // groupID
    const int t    = lane & 3;    // thread-in-group

    // ---- stage weights (tf32-rounded) ----
    for (int i = tid; i < 128 * 48; i += NTHR) {
        int n = i / 48, k = i - n * 48;
        w0s[n * W0_STR + k] = tf32f(w0[i]);
    }
    for (int i = tid; i < 16 * 128; i += NTHR) {
        int r = i >> 7, c = i & 127;
        w1s[r * W1_STR + c] = tf32f(w1[i]);
    }
    if (tid < 128) b0s[tid] = b0[tid];
    __syncthreads();

    // ---- GEMM1 warp tiling: M=32 (2 m16 tiles) x N=32 per warp ----
    const int mrow0 = (wid & 3) * 32;    // hid row base
    const int cg    = wid >> 2;          // col group: cols [32*cg, +32) of each 64-px sub

    float biasv[2][2];
    #pragma unroll
    for (int mt = 0; mt < 2; mt++) {
        biasv[mt][0] = b0s[mrow0 + 16 * mt + g];
        biasv[mt][1] = b0s[mrow0 + 16 * mt + g + 8];
    }

    const int px_  = tid & 127;          // feature pixel for this thread
    const int fsel = tid >> 7;           // which 8 channels
    const int fpy  = px_ >> 5, fpx = px_ & 31;

    // halo loader role: threads 0..203 each load 16 channels of one (hy,hx)
    const int hpos = tid;
    const int hhy  = hpos / TPW;
    const int hhx  = hpos - hhy * TPW;

    const int tile0 = blockIdx.x * TILES_PER_CTA;
    for (int it = 0; it < TILES_PER_CTA; ++it) {
        const int tile = tile0 + it;
        const int b    = tile >> 11;
        const int rem  = tile & 2047;
        const int gh0  = (rem >> 4) * 4;
        const int gw0  = (rem & 15) * 32;

        __syncthreads();   // prev tile's readers of xs/ms/Hs done

        // ---- halo load (zero pad): 204 workers x 16 channels ----
        if (hpos < XS_CH) {
            const int gh = gh0 + hhy - 1, gw = gw0 + hhx - 1;
            if (gh >= 0 && gh < HW && gw >= 0 && gw < HW) {
                const float* gp = x + ((size_t)b << 22) + ((size_t)(gh << 9) + gw);
                #pragma unroll
                for (int c = 0; c < 16; c++)
                    xs[c * XS_CH + hpos] = gp[(size_t)c << 18];
            } else {
                #pragma unroll
                for (int c = 0; c < 16; c++)
                    xs[c * XS_CH + hpos] = 0.f;
            }
        }
        if (tid < 128) {
            int gh = gh0 + (tid >> 5), gw = gw0 + (tid & 31);
            ms[tid] = rand_u[((size_t)b << 18) + (gh << 9) + gw] > 0.5f ? 1.f : 0.f;
        }
        __syncthreads();

        // ---- features: this thread does 8 channels for pixel px_ ----
        {
            const int cb = fsel * 8;
            #pragma unroll
            for (int c = 0; c < 8; c++) {
                const float* p = xs + (cb + c) * XS_CH + fpy * TPW + fpx;
                float a00 = p[0],       a01 = p[1],           a02 = p[2];
                float a10 = p[TPW],     a11 = p[TPW + 1],     a12 = p[TPW + 2];
                float a20 = p[2*TPW],   a21 = p[2*TPW + 1],   a22 = p[2*TPW + 2];
                float gx = (a02 - a00) + 2.f * (a12 - a10) + (a22 - a20);
                float gy = (a20 - a00) + 2.f * (a21 - a01) + (a22 - a02);
                ys[(cb + c) * YS_STR + px_]      = tf32f(a11);
                ys[(16 + cb + c) * YS_STR + px_] = tf32f(gx);
                ys[(32 + cb + c) * YS_STR + px_] = tf32f(gy);
            }
        }
        __syncthreads();

        // ---- GEMM1: per warp M=32 x N=32 per sub; B shared across m-tiles ----
        float acc[2][2][4][4];   // [sub][mt][j][frag]
        #pragma unroll
        for (int sub = 0; sub < 2; sub++)
            #pragma unroll
            for (int mt = 0; mt < 2; mt++)
                #pragma unroll
                for (int j = 0; j < 4; j++) {
                    acc[sub][mt][j][0] = biasv[mt][0]; acc[sub][mt][j][1] = biasv[mt][0];
                    acc[sub][mt][j][2] = biasv[mt][1]; acc[sub][mt][j][3] = biasv[mt][1];
                }
        #pragma unroll
        for (int s = 0; s < 6; s++) {
            // A fragments for both m-tiles, R4's intra-tile pattern, base mrow0+16mt
            float af[2][4];
            #pragma unroll
            for (int mt = 0; mt < 2; mt++) {
                const int r0 = mrow0 + 16 * mt + g;
                af[mt][0] = w0s[r0 * W0_STR + 8 * s + t];
                af[mt][1] = w0s[(r0 + 8) * W0_STR + 8 * s + t];
                af[mt][2] = w0s[r0 * W0_STR + 8 * s + t + 4];
                af[mt][3] = w0s[(r0 + 8) * W0_STR + 8 * s + t + 4];
            }
            #pragma unroll
            for (int sub = 0; sub < 2; sub++) {
                const float* yb0 = ys + (8 * s + t) * YS_STR + 64 * sub + 32 * cg + g;
                const float* yb1 = ys + (8 * s + t + 4) * YS_STR + 64 * sub + 32 * cg + g;
                #pragma unroll
                for (int j = 0; j < 4; j++) {
                    float bv0 = yb0[8 * j], bv1 = yb1[8 * j];
                    mma8(acc[sub][0][j], af[0], bv0, bv1);
                    mma8(acc[sub][1][j], af[1], bv0, bv1);
                }
            }
        }
        __syncthreads();   // all ys reads done; region becomes H

        // ---- relu -> tf32 -> H[hid][128] (R4 store pattern, shifted bases) ----
        #pragma unroll
        for (int sub = 0; sub < 2; sub++) {
            #pragma unroll
            for (int mt = 0; mt < 2; mt++) {
                const int hr = mrow0 + 16 * mt + g;
                #pragma unroll
                for (int j = 0; j < 4; j++) {
                    int cc = 64 * sub + 32 * cg + 8 * j + 2 * t;
                    float2 v0 = { tf32f(fmaxf(acc[sub][mt][j][0], 0.f)),
                                  tf32f(fmaxf(acc[sub][mt][j][1], 0.f)) };
                    float2 v1 = { tf32f(fmaxf(acc[sub][mt][j][2], 0.f)),
                                  tf32f(fmaxf(acc[sub][mt][j][3], 0.f)) };
                    *(float2*)(Hs + hr * H_STR + cc)       = v0;
                    *(float2*)(Hs + (hr + 8) * H_STR + cc) = v1;
                }
            }
        }
        __syncthreads();   // H ready

        // ---- GEMM2: both halves in one k-loop (R9 verbatim) ----
        float acc2[2][4] = {{0.f,0.f,0.f,0.f},{0.f,0.f,0.f,0.f}};
        #pragma unroll
        for (int s = 0; s < 16; s++) {
            float aa[4];
            aa[0] = w1s[g * W1_STR + 8 * s + t];
            aa[1] = w1s[(g + 8) * W1_STR + 8 * s + t];
            aa[2] = w1s[g * W1_STR + 8 * s + t + 4];
            aa[3] = w1s[(g + 8) * W1_STR + 8 * s + t + 4];
            const float* hb0 = Hs + (8 * s + t) * H_STR + 8 * wid + g;
            const float* hb1 = Hs + (8 * s + t + 4) * H_STR + 8 * wid + g;
            mma8(acc2[0], aa, hb0[0],  hb1[0]);
            mma8(acc2[1], aa, hb0[64], hb1[64]);
        }

        // ---- epilogue per half (R4 EXACT, pxb = 64*sub) ----
        #pragma unroll
        for (int sub = 0; sub < 2; sub++) {
            const int cl = 8 * wid + 2 * t;
            const int p  = 64 * sub + cl;
            const int py = p >> 5, pxw = p & 31;
            const float m0 = ms[p], m1 = ms[p + 1];
            const int ch = g, ch2 = g + 8;
            const float* xc0 = xs + ch  * XS_CH + (py + 1) * TPW + pxw + 1;
            const float* xc1 = xs + ch2 * XS_CH + (py + 1) * TPW + pxw + 1;
            size_t o0 = ((size_t)(b * 16 + ch)  << 18) + ((size_t)(gh0 + py) << 9) + gw0 + pxw;
            size_t o1 = ((size_t)(b * 16 + ch2) << 18) + ((size_t)(gh0 + py) << 9) + gw0 + pxw;
            float2 v0 = { xc0[0] + acc2[sub][0] * m0, xc0[1] + acc2[sub][1] * m1 };
            float2 v1 = { xc1[0] + acc2[sub][2] * m0, xc1[1] + acc2[sub][3] * m1 };
            *(float2*)(out + o0) = v0;
            *(float2*)(out + o1) = v1;
        }
    }
}

extern "C" void kernel_launch(void* const* d_in, const int* in_sizes, int n_in,
                              void* d_out, int out_size)
{
    const float* x      = (const float*)d_in[0];
    const float* w0     = (const float*)d_in[1];
    const float* b0     = (const float*)d_in[2];
    const float* w1     = (const float*)d_in[3];
    const float* rand_u = (const float*)d_in[4];
    float* out = (float*)d_out;

    const int smem_bytes = SM_FLOATS * sizeof(float);   // 118784 B
    cudaFuncSetAttribute(ca_mma_kernel, cudaFuncAttributeMaxDynamicSharedMemorySize,
                         smem_bytes);
    dim3 grid(N_TILES / TILES_PER_CTA);  // 4096 CTAs
    ca_mma_kernel<<<grid, NTHR, smem_bytes>>>(x, w0, b0, w1, rand_u, out);
}

// round 11
// speedup vs baseline: 1.4376x; 1.4376x over previous
#include <cuda_runtime.h>
#include <cstdint>

#define HW   512
#define NTHR 256
#define TPW  34
#define TPH  6
#define XS_CH (TPH * TPW)        // 204
#define TILES_PER_CTA 4
#define N_TILES 8192             // 4 batches * 16 * 128 tiles of 32x4

// smem layout (float offsets) — identical to R9
// Region at YS_OFF is time-shared: w0 staging (startup) -> per tile: ys (features),
// then H (after GEMM1 ys-reads complete, protected by a barrier).
#define XS_OFF 0                 // [16][204] = 3264
#define YS_STR 136
#define YS_OFF 3264              // ys: [48][136] = 6528
#define H_STR  136
#define H_OFF  3264              // H: [128][136] used cols 0..127 -> 17408
#define W0_OFF 3264              // staging only (6144 <= 17408)
#define REGION 17408
#define W1_STR 132
#define W1_OFF (YS_OFF + REGION)        // 20672 ; [16][132] = 2112
#define B0_OFF (W1_OFF + 2112)          // 22784
#define MS_OFF (B0_OFF + 128)           // 22912
#define SM_FLOATS (MS_OFF + 128)        // 23040 floats = 92160 B

__device__ __forceinline__ float tf32f(float f) {
    uint32_t u;
    asm("cvt.rna.tf32.f32 %0, %1;" : "=r"(u) : "f"(f));
    return __uint_as_float(u);
}

// D += A(16x8) * B(8x8), tf32 inputs, f32 accumulate
__device__ __forceinline__ void mma8(float* d, const float* a, float b0, float b1) {
    asm("mma.sync.aligned.m16n8k8.row.col.f32.tf32.tf32.f32 "
        "{%0,%1,%2,%3}, {%4,%5,%6,%7}, {%8,%9}, {%0,%1,%2,%3};"
        : "+f"(d[0]), "+f"(d[1]), "+f"(d[2]), "+f"(d[3])
        : "r"(__float_as_uint(a[0])), "r"(__float_as_uint(a[1])),
          "r"(__float_as_uint(a[2])), "r"(__float_as_uint(a[3])),
          "r"(__float_as_uint(b0)), "r"(__float_as_uint(b1)));
}

__global__ __launch_bounds__(NTHR, 2)
void ca_mma_kernel(const float* __restrict__ x,
                   const float* __restrict__ w0,
                   const float* __restrict__ b0,
                   const float* __restrict__ w1,
                   const float* __restrict__ rand_u,
                   float* __restrict__ out)
{
    extern __shared__ float sm[];
    float* xs  = sm + XS_OFF;
    float* ys  = sm + YS_OFF;
    float* Hs  = sm + H_OFF;
    float* w0s = sm + W0_OFF;   // startup staging, aliased
    float* w1s = sm + W1_OFF;
    float* b0s = sm + B0_OFF;
    float* ms  = sm + MS_OFF;

    const int tid  = threadIdx.x;
    const int lane = tid & 31;
    const int wid  = tid >> 5;
    const int g    = lane >> 2;   // groupID
    const int t    = lane & 3;    // thread-in-group

    // ---- stage weights (tf32-rounded) ----
    for (int i = tid; i < 128 * 48; i += NTHR) w0s[i] = tf32f(w0[i]);
    for (int i = tid; i < 16 * 128; i += NTHR) {
        int r = i >> 7, c = i & 127;
        w1s[r * W1_STR + c] = tf32f(w1[i]);
    }
    if (tid < 128) b0s[tid] = b0[tid];
    __syncthreads();

    // ---- persistent W0 A-fragments: warp wid owns hid rows [16*wid, 16*wid+16) ----
    float a1f[6][4];
    {
        const int r0 = 16 * wid + g;
        #pragma unroll
        for (int s = 0; s < 6; s++) {
            a1f[s][0] = w0s[r0 * 48 + 8 * s + t];
            a1f[s][1] = w0s[(r0 + 8) * 48 + 8 * s + t];
            a1f[s][2] = w0s[r0 * 48 + 8 * s + t + 4];
            a1f[s][3] = w0s[(r0 + 8) * 48 + 8 * s + t + 4];
        }
    }
    const float bias0 = b0s[16 * wid + g];
    const float bias1 = b0s[16 * wid + g + 8];

    const int px_  = tid & 127;          // feature pixel for this thread
    const int fsel = tid >> 7;           // which 8 channels
    const int fpy  = px_ >> 5, fpx = px_ & 31;

    // halo loader role: threads 0..203 each load 16 channels of one (hy,hx)
    const int hpos = tid;                // valid if < 204
    const int hhy  = hpos / TPW;
    const int hhx  = hpos - hhy * TPW;

    const int tile0 = blockIdx.x * TILES_PER_CTA;
    for (int it = 0; it < TILES_PER_CTA; ++it) {
        const int tile = tile0 + it;
        const int b    = tile >> 11;
        const int rem  = tile & 2047;
        const int gh0  = (rem >> 4) * 4;
        const int gw0  = (rem & 15) * 32;

        __syncthreads();   // prev tile's readers of xs/ms/Hs done

        // ---- halo load (zero pad): 204 workers x 16 channels ----
        if (hpos < XS_CH) {
            const int gh = gh0 + hhy - 1, gw = gw0 + hhx - 1;
            if (gh >= 0 && gh < HW && gw >= 0 && gw < HW) {
                const float* gp = x + (((size_t)b << 22)) + ((size_t)(gh << 9) + gw);
                #pragma unroll
                for (int c = 0; c < 16; c++)
                    xs[c * XS_CH + hpos] = gp[(size_t)c << 18];
            } else {
                #pragma unroll
                for (int c = 0; c < 16; c++)
                    xs[c * XS_CH + hpos] = 0.f;
            }
        }
        if (tid < 128) {
            int gh = gh0 + (tid >> 5), gw = gw0 + (tid & 31);
            ms[tid] = rand_u[((size_t)b << 18) + (gh << 9) + gw] > 0.5f ? 1.f : 0.f;
        }
        __syncthreads();

        // ---- features: this thread does 8 channels for pixel px_ ----
        {
            const int cb = fsel * 8;
            #pragma unroll
            for (int c = 0; c < 8; c++) {
                const float* p = xs + (cb + c) * XS_CH + fpy * TPW + fpx;
                float a00 = p[0],       a01 = p[1],           a02 = p[2];
                float a10 = p[TPW],     a11 = p[TPW + 1],     a12 = p[TPW + 2];
                float a20 = p[2*TPW],   a21 = p[2*TPW + 1],   a22 = p[2*TPW + 2];
                float gx = (a02 - a00) + 2.f * (a12 - a10) + (a22 - a20);
                float gy = (a20 - a00) + 2.f * (a21 - a01) + (a22 - a02);
                ys[(cb + c) * YS_STR + px_]      = tf32f(a11);
                ys[(16 + cb + c) * YS_STR + px_] = tf32f(gx);
                ys[(32 + cb + c) * YS_STR + px_] = tf32f(gy);
            }
        }
        __syncthreads();

        // ---- GEMM1 for BOTH 64-px halves (exact R4 indices, looped over sub) ----
        float acc[2][8][4];
        #pragma unroll
        for (int sub = 0; sub < 2; sub++) {
            const int pxb = sub * 64;
            #pragma unroll
            for (int j = 0; j < 8; j++) {
                acc[sub][j][0] = bias0; acc[sub][j][1] = bias0;
                acc[sub][j][2] = bias1; acc[sub][j][3] = bias1;
            }
            #pragma unroll
            for (int s = 0; s < 6; s++) {
                const float* yb0 = ys + (8 * s + t) * YS_STR + pxb + g;
                const float* yb1 = ys + (8 * s + t + 4) * YS_STR + pxb + g;
                #pragma unroll
                for (int j = 0; j < 8; j++)
                    mma8(acc[sub][j], a1f[s], yb0[8 * j], yb1[8 * j]);
            }
        }
        __syncthreads();   // all ys reads done; region becomes H

        // ---- relu -> tf32 -> H[hid][128] (same addrs as R9, float2-paired) ----
        {
            const int hr = 16 * wid + g;
            #pragma unroll
            for (int sub = 0; sub < 2; sub++) {
                #pragma unroll
                for (int j = 0; j < 8; j++) {
                    int cc = 64 * sub + 8 * j + 2 * t;
                    float2 v0 = { tf32f(fmaxf(acc[sub][j][0], 0.f)),
                                  tf32f(fmaxf(acc[sub][j][1], 0.f)) };
                    float2 v1 = { tf32f(fmaxf(acc[sub][j][2], 0.f)),
                                  tf32f(fmaxf(acc[sub][j][3], 0.f)) };
                    *(float2*)(Hs + hr * H_STR + cc)       = v0;
                    *(float2*)(Hs + (hr + 8) * H_STR + cc) = v1;
                }
            }
        }
        __syncthreads();   // H ready

        // ---- GEMM2: both halves in one k-loop (A fragments loaded once) ----
        float acc2[2][4] = {{0.f,0.f,0.f,0.f},{0.f,0.f,0.f,0.f}};
        #pragma unroll
        for (int s = 0; s < 16; s++) {
            float aa[4];
            aa[0] = w1s[g * W1_STR + 8 * s + t];
            aa[1] = w1s[(g + 8) * W1_STR + 8 * s + t];
            aa[2] = w1s[g * W1_STR + 8 * s + t + 4];
            aa[3] = w1s[(g + 8) * W1_STR + 8 * s + t + 4];
            const float* hb0 = Hs + (8 * s + t) * H_STR + 8 * wid + g;
            const float* hb1 = Hs + (8 * s + t + 4) * H_STR + 8 * wid + g;
            mma8(acc2[0], aa, hb0[0],  hb1[0]);
            mma8(acc2[1], aa, hb0[64], hb1[64]);
        }

        // ---- epilogue per half (R4 EXACT, pxb = 64*sub) ----
        #pragma unroll
        for (int sub = 0; sub < 2; sub++) {
            const int cl = 8 * wid + 2 * t;      // chunk-local col (even)
            const int p  = 64 * sub + cl;        // pixel 0..126 (even)
            const int py = p >> 5, pxw = p & 31;
            const float m0 = ms[p], m1 = ms[p + 1];
            const int ch = g, ch2 = g + 8;
            const float* xc0 = xs + ch  * XS_CH + (py + 1) * TPW + pxw + 1;
            const float* xc1 = xs + ch2 * XS_CH + (py + 1) * TPW + pxw + 1;
            size_t o0 = ((size_t)(b * 16 + ch)  << 18) + ((size_t)(gh0 + py) << 9) + gw0 + pxw;
            size_t o1 = ((size_t)(b * 16 + ch2) << 18) + ((size_t)(gh0 + py) << 9) + gw0 + pxw;
            float2 v0 = { xc0[0] + acc2[sub][0] * m0, xc0[1] + acc2[sub][1] * m1 };
            float2 v1 = { xc1[0] + acc2[sub][2] * m0, xc1[1] + acc2[sub][3] * m1 };
            *(float2*)(out + o0) = v0;
            *(float2*)(out + o1) = v1;
        }
    }
}

extern "C" void kernel_launch(void* const* d_in, const int* in_sizes, int n_in,
                              void* d_out, int out_size)
{
    const float* x      = (const float*)d_in[0];
    const float* w0     = (const float*)d_in[1];
    const float* b0     = (const float*)d_in[2];
    const float* w1     = (const float*)d_in[3];
    const float* rand_u = (const float*)d_in[4];
    float* out = (float*)d_out;

    const int smem_bytes = SM_FLOATS * sizeof(float);   // 92160 B
    cudaFuncSetAttribute(ca_mma_kernel, cudaFuncAttributeMaxDynamicSharedMemorySize,
                         smem_bytes);
    dim3 grid(N_TILES / TILES_PER_CTA);  // 2048 CTAs
    ca_mma_kernel<<<grid, NTHR, smem_bytes>>>(x, w0, b0, w1, rand_u, out);
}